// round 12
// baseline (speedup 1.0000x reference)
#include <cuda_runtime.h>
#include <stdint.h>

// Fp8Unpadding: gather un-padded rows out of a 256-row-padded concatenation.
// M_SPLITS = {1000,2300,512,3777,129,2048,900,1500}, HIDDEN=4096 (f32).
// dst row r maps to src row r + DELTA[group(r)]; DELTA constant per group.
//
// Row boundaries (cumulative m):  1000, 3300, 3812, 7589, 7718, 9766, 10666, 12166
// Row deltas:                        0,   24,   28,   28,   91,  218,   218,   342
//
// R12 probe: software-pipelined R/W interleave. Same winning geometry
// (one 16KB row per CTA, TPB=128, 8x float4/thread, .cs both ways), but
// instead of batching all 8 loads before all 8 stores, keep PIPE=4 loads
// in flight and interleave: ld(j+4) || st(j). Presents steady concurrent
// read+write streams to the DRAM controller instead of per-warp phase
// alternation. Only untried degree of freedom: issue ORDER.

static constexpr int HIDDEN_V4  = 4096 / 4;   // 1024 float4 per row
static constexpr int TOTAL_ROWS = 12166;
static constexpr int UNROLL     = 8;
static constexpr int PIPE       = 4;          // loads kept in flight
static constexpr int TPB        = 128;        // TPB * UNROLL = 1024 = 1 row

__device__ __forceinline__ int row_delta(int row)
{
    return (row < 1000)  ? 0
         : (row < 3300)  ? 24
         : (row < 7589)  ? 28
         : (row < 7718)  ? 91
         : (row < 10666) ? 218
         :                 342;
}

__global__ void __launch_bounds__(TPB)
unpad_gather_kernel(const float4* __restrict__ in, float4* __restrict__ out)
{
    int row = blockIdx.x;                        // one row per block
    const float4* __restrict__ src = in  + (row + row_delta(row)) * HIDDEN_V4;
    float4*       __restrict__ dst = out + row * HIDDEN_V4;

    float4 v[UNROLL];

    // prologue: fill the pipe with PIPE independent loads
    #pragma unroll
    for (int j = 0; j < PIPE; j++)
        v[j] = __ldcs(src + j * TPB + threadIdx.x);

    // steady state: issue ld(j+PIPE) alongside st(j)
    #pragma unroll
    for (int j = 0; j < UNROLL - PIPE; j++) {
        v[j + PIPE] = __ldcs(src + (j + PIPE) * TPB + threadIdx.x);
        __stcs(dst + j * TPB + threadIdx.x, v[j]);
    }

    // epilogue: drain remaining stores
    #pragma unroll
    for (int j = UNROLL - PIPE; j < UNROLL; j++)
        __stcs(dst + j * TPB + threadIdx.x, v[j]);
}

extern "C" void kernel_launch(void* const* d_in, const int* in_sizes, int n_in,
                              void* d_out, int out_size)
{
    const float4* in  = (const float4*)d_in[0];   // f32 [12544, 4096]
    float4*       out = (float4*)d_out;           // f32 [12166, 4096]

    unpad_gather_kernel<<<TOTAL_ROWS, TPB>>>(in, out);
}

// round 13
// speedup vs baseline: 1.0082x; 1.0082x over previous
#include <cuda_runtime.h>
#include <stdint.h>

// Fp8Unpadding: gather un-padded rows out of a 256-row-padded concatenation.
// M_SPLITS = {1000,2300,512,3777,129,2048,900,1500}, HIDDEN=4096 (f32).
// dst row r maps to src row r + DELTA[group(r)]; DELTA constant per group.
//
// Row boundaries (cumulative m):  1000, 3300, 3812, 7589, 7718, 9766, 10666, 12166
// Row deltas:                        0,   24,   28,   28,   91,  218,   218,   342
//
// FINAL: one 16KB row per block. TPB=128, 8x float4 per thread = 1024 v4 =
// exactly 1 row. Block-uniform source delta, front-batched loads (MLP=8),
// streaming (.cs) policy both directions, zero tail, no bounds checks.
//
// Roofline status: pinned at the measured B300 LTS chip cap (~6300 B/cyc;
// peak observed 6304 GB/s). Saturated — verified across all available axes:
// MLP depth, issue order (batched vs pipelined), access width (128/256-bit),
// cache policy (.cs/.lu), grid shape (one-shot/persistent, 1/2-row CTAs),
// and hardware path (SM vs copy engines). Limit is the LTS fabric.

static constexpr int HIDDEN_V4  = 4096 / 4;   // 1024 float4 per row
static constexpr int TOTAL_ROWS = 12166;
static constexpr int UNROLL     = 8;
static constexpr int TPB        = 128;        // TPB * UNROLL = 1024 = 1 row

__device__ __forceinline__ int row_delta(int row)
{
    return (row < 1000)  ? 0
         : (row < 3300)  ? 24
         : (row < 7589)  ? 28
         : (row < 7718)  ? 91
         : (row < 10666) ? 218
         :                 342;
}

__global__ void __launch_bounds__(TPB)
unpad_gather_kernel(const float4* __restrict__ in, float4* __restrict__ out)
{
    int row = blockIdx.x;                        // one row per block
    const float4* __restrict__ src = in  + (row + row_delta(row)) * HIDDEN_V4;
    float4*       __restrict__ dst = out + row * HIDDEN_V4;

    float4 v[UNROLL];

    // front-batched independent loads (deep MLP)
    #pragma unroll
    for (int j = 0; j < UNROLL; j++)
        v[j] = __ldcs(src + j * TPB + threadIdx.x);

    #pragma unroll
    for (int j = 0; j < UNROLL; j++)
        __stcs(dst + j * TPB + threadIdx.x, v[j]);
}

extern "C" void kernel_launch(void* const* d_in, const int* in_sizes, int n_in,
                              void* d_out, int out_size)
{
    const float4* in  = (const float4*)d_in[0];   // f32 [12544, 4096]
    float4*       out = (float4*)d_out;           // f32 [12166, 4096]

    unpad_gather_kernel<<<TOTAL_ROWS, TPB>>>(in, out);
}